// round 2
// baseline (speedup 1.0000x reference)
#include <cuda_runtime.h>

#define EPS 1e-6f
#define BLOCK 128
#define ROWPAD 25          // 24 floats/row padded to 25 (coprime with 32 banks)
#define MAX_PARTIALS 8192

__device__ float2 g_partials[MAX_PARTIALS];
__device__ unsigned int g_count = 0;

__device__ __forceinline__ float norm2f(float x, float y) {
    return sqrtf(x * x + y * y);
}

__global__ void __launch_bounds__(BLOCK)
gsc_fused_kernel(const float* __restrict__ pred,
                 const float* __restrict__ gt,
                 float* __restrict__ out,
                 int nrows)
{
    __shared__ float smP[BLOCK * ROWPAD];
    __shared__ float smG[BLOCK * ROWPAD];
    __shared__ float sL[BLOCK / 32];
    __shared__ float sC[BLOCK / 32];
    __shared__ int sIsLast;

    const int tid  = threadIdx.x;
    const int base = blockIdx.x * BLOCK;
    const int rowsHere = min(BLOCK, nrows - base);
    const int nf4 = rowsHere * 6;          // float4s per tensor in this tile

    // ---- coalesced gmem -> smem staging (float4, consecutive addresses) ----
    {
        const float4* p4 = reinterpret_cast<const float4*>(pred) + (size_t)base * 6;
        const float4* q4 = reinterpret_cast<const float4*>(gt)   + (size_t)base * 6;
        #pragma unroll
        for (int i = 0; i < 6; i++) {
            const int j = tid + BLOCK * i;
            if (j < nf4) {
                const int row = j / 6;
                const int col = 4 * (j % 6);
                float4 v = p4[j];
                float* d = &smP[row * ROWPAD + col];
                d[0] = v.x; d[1] = v.y; d[2] = v.z; d[3] = v.w;
                float4 w = q4[j];
                float* e = &smG[row * ROWPAD + col];
                e[0] = w.x; e[1] = w.y; e[2] = w.z; e[3] = w.w;
            }
        }
    }
    __syncthreads();

    // ---- per-row loss ----
    float L = 0.0f, cnt = 0.0f;
    if (tid < rowsHere) {
        const float* P = &smP[tid * ROWPAD];
        const float* G = &smG[tid * ROWPAD];

        float px[4], py[4], gx[4], gy[4];
        int nv = 0;
        #pragma unroll
        for (int k = 0; k < 8; k++) {
            const bool vis = (P[3*k+2] > 0.5f) && (G[3*k+2] > 0.5f);
            if (vis) {
                const float ax = P[3*k], ay = P[3*k+1];
                const float bx = G[3*k], by = G[3*k+1];
                if (nv == 0)      { px[0]=ax; py[0]=ay; gx[0]=bx; gy[0]=by; }
                else if (nv == 1) { px[1]=ax; py[1]=ay; gx[1]=bx; gy[1]=by; }
                else if (nv == 2) { px[2]=ax; py[2]=ay; gx[2]=bx; gy[2]=by; }
                else if (nv == 3) { px[3]=ax; py[3]=ay; gx[3]=bx; gy[3]=by; }
                nv++;
            }
        }

        if (nv >= 4) {
            // ---- L_shape ----
            const float pred_cr = norm2f(px[2]-px[0], py[2]-py[0]) /
                                  (norm2f(px[3]-px[1], py[3]-py[1]) + EPS);
            const float gt_cr   = norm2f(gx[2]-gx[0], gy[2]-gy[0]) /
                                  (norm2f(gx[3]-gx[1], gy[3]-gy[1]) + EPS);
            const float L_shape = fabsf(pred_cr - gt_cr);

            // ---- L_edge ----
            const float v12x = px[1]-px[0], v12y = py[1]-py[0];
            const float v23x = px[2]-px[1], v23y = py[2]-py[1];
            const float v34x = px[3]-px[2], v34y = py[3]-py[2];
            const float v41x = px[0]-px[3], v41y = py[0]-py[3];
            const float l12 = norm2f(v12x, v12y);
            const float l23 = norm2f(v23x, v23y);
            const float l34 = norm2f(v34x, v34y);
            const float l41 = norm2f(v41x, v41y);

            const float par1 = fabsf(l12 - l34) / (l12 + l34 + EPS);
            const float par2 = fabsf(l23 - l41) / (l23 + l41 + EPS);
            const float dot1 = fabsf((v12x*v41x + v12y*v41y) / (l12*l41 + EPS));
            const float dot2 = fabsf((v12x*v23x + v12y*v23y) / (l12*l23 + EPS));
            const float dot3 = fabsf((v23x*v34x + v23y*v34y) / (l23*l34 + EPS));
            const float dot4 = fabsf((v34x*v41x + v34y*v41y) / (l34*l41 + EPS));
            const float L_edge = (par1 + par2) * 0.5f + (dot1 + dot2 + dot3 + dot4) * 0.25f;

            // ---- L_pos ----
            float dist = 0.0f;
            #pragma unroll
            for (int i = 0; i < 4; i++)
                dist += norm2f(px[i]-gx[i], py[i]-gy[i]);
            dist *= 0.25f;

            const float pax1 = px[1]-px[0], pay1 = py[1]-py[0];
            const float pax2 = px[2]-px[0], pay2 = py[2]-py[0];
            const float pax3 = px[3]-px[0], pay3 = py[3]-py[0];
            const float pred_area = 0.5f * fabsf(pax1*pay2 - pay1*pax2)
                                  + 0.5f * fabsf(pax2*pay3 - pay2*pax3);
            const float gax1 = gx[1]-gx[0], gay1 = gy[1]-gy[0];
            const float gax2 = gx[2]-gx[0], gay2 = gy[2]-gy[0];
            const float gax3 = gx[3]-gx[0], gay3 = gy[3]-gy[0];
            const float gt_area = 0.5f * fabsf(gax1*gay2 - gay1*gax2)
                                + 0.5f * fabsf(gax2*gay3 - gay2*gax3);
            const float area_ratio = fabsf(pred_area - gt_area) / (gt_area + EPS);

            const float pmx = 0.25f * (px[0]+px[1]+px[2]+px[3]);
            const float pmy = 0.25f * (py[0]+py[1]+py[2]+py[3]);
            const float gmx = 0.25f * (gx[0]+gx[1]+gx[2]+gx[3]);
            const float gmy = 0.25f * (gy[0]+gy[1]+gy[2]+gy[3]);
            float rel_cons = 0.0f;
            #pragma unroll
            for (int i = 0; i < 4; i++)
                rel_cons += norm2f((px[i]-pmx) - (gx[i]-gmx),
                                   (py[i]-pmy) - (gy[i]-gmy));
            rel_cons *= 0.25f;

            const float L_pos = 0.4f * dist + 0.3f * area_ratio + 0.3f * rel_cons;

            L = 0.4f * L_shape + 0.3f * L_edge + 0.3f * L_pos;
            cnt = 1.0f;
        }
    }

    // ---- block reduction (deterministic tree) ----
    #pragma unroll
    for (int off = 16; off > 0; off >>= 1) {
        L   += __shfl_down_sync(0xffffffffu, L,   off);
        cnt += __shfl_down_sync(0xffffffffu, cnt, off);
    }
    const int warp = tid >> 5;
    const int lane = tid & 31;
    if (lane == 0) { sL[warp] = L; sC[warp] = cnt; }
    __syncthreads();
    if (tid == 0) {
        float tL = 0.0f, tC = 0.0f;
        #pragma unroll
        for (int w = 0; w < BLOCK / 32; w++) { tL += sL[w]; tC += sC[w]; }
        g_partials[blockIdx.x] = make_float2(tL, tC);
        __threadfence();
        const unsigned int old = atomicAdd(&g_count, 1u);
        sIsLast = (old == gridDim.x - 1) ? 1 : 0;
    }
    __syncthreads();

    // ---- last block: final reduction over all partials (fixed order) ----
    if (sIsLast) {
        float fL = 0.0f, fC = 0.0f;
        const int nblocks = gridDim.x;
        for (int i = tid; i < nblocks; i += BLOCK) {
            float2 v = g_partials[i];
            fL += v.x;
            fC += v.y;
        }
        #pragma unroll
        for (int off = 16; off > 0; off >>= 1) {
            fL += __shfl_down_sync(0xffffffffu, fL, off);
            fC += __shfl_down_sync(0xffffffffu, fC, off);
        }
        if (lane == 0) { sL[warp] = fL; sC[warp] = fC; }
        __syncthreads();
        if (tid == 0) {
            float tL = 0.0f, tC = 0.0f;
            #pragma unroll
            for (int w = 0; w < BLOCK / 32; w++) { tL += sL[w]; tC += sC[w]; }
            out[0] = (tC > 0.5f) ? (tL / tC) : 0.0f;
            g_count = 0;   // reset for next graph replay
        }
    }
}

extern "C" void kernel_launch(void* const* d_in, const int* in_sizes, int n_in,
                              void* d_out, int out_size)
{
    const float* pred = (const float*)d_in[0];
    const float* gt   = (const float*)d_in[1];
    float* out = (float*)d_out;

    const int nrows = in_sizes[0] / 24;   // B*K*3 floats, K=8 -> 24 per row
    int nblocks = (nrows + BLOCK - 1) / BLOCK;   // 524288/128 = 4096
    if (nblocks > MAX_PARTIALS) nblocks = MAX_PARTIALS;

    gsc_fused_kernel<<<nblocks, BLOCK>>>(pred, gt, out, nrows);
}

// round 4
// speedup vs baseline: 1.0650x; 1.0650x over previous
#include <cuda_runtime.h>

#define EPS 1e-6f
#define BLOCK 128
#define RP4 7                 // row pad: 7 float4 = 28 floats = 112B (7t+i mod 8 bijective)
#define MAX_PARTIALS 8192

__device__ float2 g_partials[MAX_PARTIALS];
__device__ unsigned int g_count = 0;

__device__ __forceinline__ float norm2f(float x, float y) {
    return sqrtf(x * x + y * y);
}

__global__ void __launch_bounds__(BLOCK)
gsc_fused_kernel(const float* __restrict__ pred,
                 const float* __restrict__ gt,
                 float* __restrict__ out,
                 int nrows)
{
    __shared__ float4 smP4[BLOCK * RP4];
    __shared__ float4 smG4[BLOCK * RP4];
    __shared__ float sL[BLOCK / 32];
    __shared__ float sC[BLOCK / 32];
    __shared__ int sIsLast;

    const int tid  = threadIdx.x;
    const int base = blockIdx.x * BLOCK;

    // ---- stage: 12 unconditional batched LDG.128 -> regs -> 12 STS.128 ----
    const float4* p4 = reinterpret_cast<const float4*>(pred) + (size_t)base * 6;
    const float4* q4 = reinterpret_cast<const float4*>(gt)   + (size_t)base * 6;

    if (base + BLOCK <= nrows) {
        float4 rp[6], rg[6];
        #pragma unroll
        for (int i = 0; i < 6; i++) rp[i] = p4[tid + BLOCK * i];
        #pragma unroll
        for (int i = 0; i < 6; i++) rg[i] = q4[tid + BLOCK * i];
        #pragma unroll
        for (int i = 0; i < 6; i++) {
            const int j = tid + BLOCK * i;
            smP4[(j / 6) * RP4 + (j % 6)] = rp[i];
            smG4[(j / 6) * RP4 + (j % 6)] = rg[i];
        }
    } else {
        const int nf4 = (nrows - base) * 6;
        #pragma unroll
        for (int i = 0; i < 6; i++) {
            const int j = tid + BLOCK * i;
            if (j < nf4) {
                smP4[(j / 6) * RP4 + (j % 6)] = p4[j];
                smG4[(j / 6) * RP4 + (j % 6)] = q4[j];
            }
        }
    }
    __syncthreads();

    // ---- per-row loss (scalar reads from padded smem) ----
    float L = 0.0f, cnt = 0.0f;
    if (base + tid < nrows) {
        const float* P = reinterpret_cast<const float*>(&smP4[tid * RP4]);
        const float* G = reinterpret_cast<const float*>(&smG4[tid * RP4]);

        float px[4], py[4], gx[4], gy[4];
        int nv = 0;
        #pragma unroll
        for (int k = 0; k < 8; k++) {
            const bool vis = (P[3*k+2] > 0.5f) && (G[3*k+2] > 0.5f);
            if (vis) {
                const float ax = P[3*k], ay = P[3*k+1];
                const float bx = G[3*k], by = G[3*k+1];
                if (nv == 0)      { px[0]=ax; py[0]=ay; gx[0]=bx; gy[0]=by; }
                else if (nv == 1) { px[1]=ax; py[1]=ay; gx[1]=bx; gy[1]=by; }
                else if (nv == 2) { px[2]=ax; py[2]=ay; gx[2]=bx; gy[2]=by; }
                else if (nv == 3) { px[3]=ax; py[3]=ay; gx[3]=bx; gy[3]=by; }
                nv++;
            }
        }

        if (nv >= 4) {
            // ---- L_shape ----
            const float pred_cr = __fdividef(norm2f(px[2]-px[0], py[2]-py[0]),
                                             norm2f(px[3]-px[1], py[3]-py[1]) + EPS);
            const float gt_cr   = __fdividef(norm2f(gx[2]-gx[0], gy[2]-gy[0]),
                                             norm2f(gx[3]-gx[1], gy[3]-gy[1]) + EPS);
            const float L_shape = fabsf(pred_cr - gt_cr);

            // ---- L_edge ----
            const float v12x = px[1]-px[0], v12y = py[1]-py[0];
            const float v23x = px[2]-px[1], v23y = py[2]-py[1];
            const float v34x = px[3]-px[2], v34y = py[3]-py[2];
            const float v41x = px[0]-px[3], v41y = py[0]-py[3];
            const float l12 = norm2f(v12x, v12y);
            const float l23 = norm2f(v23x, v23y);
            const float l34 = norm2f(v34x, v34y);
            const float l41 = norm2f(v41x, v41y);

            const float par1 = __fdividef(fabsf(l12 - l34), l12 + l34 + EPS);
            const float par2 = __fdividef(fabsf(l23 - l41), l23 + l41 + EPS);
            const float dot1 = fabsf(__fdividef(v12x*v41x + v12y*v41y, l12*l41 + EPS));
            const float dot2 = fabsf(__fdividef(v12x*v23x + v12y*v23y, l12*l23 + EPS));
            const float dot3 = fabsf(__fdividef(v23x*v34x + v23y*v34y, l23*l34 + EPS));
            const float dot4 = fabsf(__fdividef(v34x*v41x + v34y*v41y, l34*l41 + EPS));
            const float L_edge = (par1 + par2) * 0.5f + (dot1 + dot2 + dot3 + dot4) * 0.25f;

            // ---- L_pos ----
            float dist = 0.0f;
            #pragma unroll
            for (int i = 0; i < 4; i++)
                dist += norm2f(px[i]-gx[i], py[i]-gy[i]);
            dist *= 0.25f;

            const float pax1 = px[1]-px[0], pay1 = py[1]-py[0];
            const float pax2 = px[2]-px[0], pay2 = py[2]-py[0];
            const float pax3 = px[3]-px[0], pay3 = py[3]-py[0];
            const float pred_area = 0.5f * fabsf(pax1*pay2 - pay1*pax2)
                                  + 0.5f * fabsf(pax2*pay3 - pay2*pax3);
            const float gax1 = gx[1]-gx[0], gay1 = gy[1]-gy[0];
            const float gax2 = gx[2]-gx[0], gay2 = gy[2]-gy[0];
            const float gax3 = gx[3]-gx[0], gay3 = gy[3]-gy[0];
            const float gt_area = 0.5f * fabsf(gax1*gay2 - gay1*gax2)
                                + 0.5f * fabsf(gax2*gay3 - gay2*gax3);
            const float area_ratio = __fdividef(fabsf(pred_area - gt_area), gt_area + EPS);

            const float pmx = 0.25f * (px[0]+px[1]+px[2]+px[3]);
            const float pmy = 0.25f * (py[0]+py[1]+py[2]+py[3]);
            const float gmx = 0.25f * (gx[0]+gx[1]+gx[2]+gx[3]);
            const float gmy = 0.25f * (gy[0]+gy[1]+gy[2]+gy[3]);
            float rel_cons = 0.0f;
            #pragma unroll
            for (int i = 0; i < 4; i++)
                rel_cons += norm2f((px[i]-pmx) - (gx[i]-gmx),
                                   (py[i]-pmy) - (gy[i]-gmy));
            rel_cons *= 0.25f;

            const float L_pos = 0.4f * dist + 0.3f * area_ratio + 0.3f * rel_cons;

            L = 0.4f * L_shape + 0.3f * L_edge + 0.3f * L_pos;
            cnt = 1.0f;
        }
    }

    // ---- block reduction (deterministic tree) ----
    #pragma unroll
    for (int off = 16; off > 0; off >>= 1) {
        L   += __shfl_down_sync(0xffffffffu, L,   off);
        cnt += __shfl_down_sync(0xffffffffu, cnt, off);
    }
    const int warp = tid >> 5;
    const int lane = tid & 31;
    if (lane == 0) { sL[warp] = L; sC[warp] = cnt; }
    __syncthreads();
    if (tid == 0) {
        float tL = 0.0f, tC = 0.0f;
        #pragma unroll
        for (int w = 0; w < BLOCK / 32; w++) { tL += sL[w]; tC += sC[w]; }
        g_partials[blockIdx.x] = make_float2(tL, tC);
        __threadfence();
        const unsigned int old = atomicAdd(&g_count, 1u);
        sIsLast = (old == gridDim.x - 1) ? 1 : 0;
    }
    __syncthreads();

    // ---- last block: final reduction (fixed order -> deterministic) ----
    if (sIsLast) {
        float fL = 0.0f, fC = 0.0f;
        const int nblocks = gridDim.x;
        for (int i = tid; i < nblocks; i += BLOCK) {
            float2 v = g_partials[i];
            fL += v.x;
            fC += v.y;
        }
        #pragma unroll
        for (int off = 16; off > 0; off >>= 1) {
            fL += __shfl_down_sync(0xffffffffu, fL, off);
            fC += __shfl_down_sync(0xffffffffu, fC, off);
        }
        if (lane == 0) { sL[warp] = fL; sC[warp] = fC; }
        __syncthreads();
        if (tid == 0) {
            float tL = 0.0f, tC = 0.0f;
            #pragma unroll
            for (int w = 0; w < BLOCK / 32; w++) { tL += sL[w]; tC += sC[w]; }
            out[0] = (tC > 0.5f) ? (tL / tC) : 0.0f;
            g_count = 0;   // reset for next graph replay
        }
    }
}

extern "C" void kernel_launch(void* const* d_in, const int* in_sizes, int n_in,
                              void* d_out, int out_size)
{
    const float* pred = (const float*)d_in[0];
    const float* gt   = (const float*)d_in[1];
    float* out = (float*)d_out;

    const int nrows = in_sizes[0] / 24;   // B*K*3 floats, K=8 -> 24 per row
    int nblocks = (nrows + BLOCK - 1) / BLOCK;   // 524288/128 = 4096
    if (nblocks > MAX_PARTIALS) nblocks = MAX_PARTIALS;

    gsc_fused_kernel<<<nblocks, BLOCK>>>(pred, gt, out, nrows);
}

// round 5
// speedup vs baseline: 1.1491x; 1.0789x over previous
#include <cuda_runtime.h>

#define EPS 1e-6f
#define BLOCK 256
#define ROWPAD 25             // 24 floats/row padded to 25 words (odd => conflict-free LDS)
#define MAX_PARTIALS 8192

__device__ float2 g_partials[MAX_PARTIALS];
__device__ unsigned int g_count = 0;

__device__ __forceinline__ float norm2f(float x, float y) {
    return sqrtf(x * x + y * y);
}

__global__ void __launch_bounds__(BLOCK)
gsc_fused_kernel(const float* __restrict__ pred,
                 const float* __restrict__ gt,
                 float* __restrict__ out,
                 int nrows)
{
    __shared__ float smP[BLOCK * ROWPAD];
    __shared__ float smG[BLOCK * ROWPAD];
    __shared__ float sL[BLOCK / 32];
    __shared__ float sC[BLOCK / 32];
    __shared__ int sIsLast;

    const int tid  = threadIdx.x;
    const int base = blockIdx.x * BLOCK;

    // ---- stage: 12 unconditional batched LDG.128 -> regs -> scalar scatter STS ----
    const float4* p4 = reinterpret_cast<const float4*>(pred) + (size_t)base * 6;
    const float4* q4 = reinterpret_cast<const float4*>(gt)   + (size_t)base * 6;

    if (base + BLOCK <= nrows) {
        float4 rp[6], rg[6];
        #pragma unroll
        for (int i = 0; i < 6; i++) rp[i] = p4[tid + BLOCK * i];
        #pragma unroll
        for (int i = 0; i < 6; i++) rg[i] = q4[tid + BLOCK * i];
        #pragma unroll
        for (int i = 0; i < 6; i++) {
            const int j = tid + BLOCK * i;
            const int w = (j / 6) * ROWPAD + (j % 6) * 4;   // word offset of this float4
            smP[w + 0] = rp[i].x; smP[w + 1] = rp[i].y;
            smP[w + 2] = rp[i].z; smP[w + 3] = rp[i].w;
            smG[w + 0] = rg[i].x; smG[w + 1] = rg[i].y;
            smG[w + 2] = rg[i].z; smG[w + 3] = rg[i].w;
        }
    } else {
        const int nf4 = (nrows - base) * 6;
        #pragma unroll
        for (int i = 0; i < 6; i++) {
            const int j = tid + BLOCK * i;
            if (j < nf4) {
                const int w = (j / 6) * ROWPAD + (j % 6) * 4;
                float4 v = p4[j];
                smP[w + 0] = v.x; smP[w + 1] = v.y; smP[w + 2] = v.z; smP[w + 3] = v.w;
                float4 u = q4[j];
                smG[w + 0] = u.x; smG[w + 1] = u.y; smG[w + 2] = u.z; smG[w + 3] = u.w;
            }
        }
    }
    __syncthreads();

    // ---- per-row loss (conflict-free scalar LDS: stride 25 is odd) ----
    float L = 0.0f, cnt = 0.0f;
    if (base + tid < nrows) {
        const float* P = &smP[tid * ROWPAD];
        const float* G = &smG[tid * ROWPAD];

        float px[4], py[4], gx[4], gy[4];
        int nv = 0;
        #pragma unroll
        for (int k = 0; k < 8; k++) {
            const bool vis = (P[3*k+2] > 0.5f) && (G[3*k+2] > 0.5f);
            if (vis) {
                const float ax = P[3*k], ay = P[3*k+1];
                const float bx = G[3*k], by = G[3*k+1];
                if (nv == 0)      { px[0]=ax; py[0]=ay; gx[0]=bx; gy[0]=by; }
                else if (nv == 1) { px[1]=ax; py[1]=ay; gx[1]=bx; gy[1]=by; }
                else if (nv == 2) { px[2]=ax; py[2]=ay; gx[2]=bx; gy[2]=by; }
                else if (nv == 3) { px[3]=ax; py[3]=ay; gx[3]=bx; gy[3]=by; }
                nv++;
            }
        }

        if (nv >= 4) {
            // ---- L_shape ----
            const float pred_cr = __fdividef(norm2f(px[2]-px[0], py[2]-py[0]),
                                             norm2f(px[3]-px[1], py[3]-py[1]) + EPS);
            const float gt_cr   = __fdividef(norm2f(gx[2]-gx[0], gy[2]-gy[0]),
                                             norm2f(gx[3]-gx[1], gy[3]-gy[1]) + EPS);
            const float L_shape = fabsf(pred_cr - gt_cr);

            // ---- L_edge ----
            const float v12x = px[1]-px[0], v12y = py[1]-py[0];
            const float v23x = px[2]-px[1], v23y = py[2]-py[1];
            const float v34x = px[3]-px[2], v34y = py[3]-py[2];
            const float v41x = px[0]-px[3], v41y = py[0]-py[3];
            const float l12 = norm2f(v12x, v12y);
            const float l23 = norm2f(v23x, v23y);
            const float l34 = norm2f(v34x, v34y);
            const float l41 = norm2f(v41x, v41y);

            const float par1 = __fdividef(fabsf(l12 - l34), l12 + l34 + EPS);
            const float par2 = __fdividef(fabsf(l23 - l41), l23 + l41 + EPS);
            const float dot1 = fabsf(__fdividef(v12x*v41x + v12y*v41y, l12*l41 + EPS));
            const float dot2 = fabsf(__fdividef(v12x*v23x + v12y*v23y, l12*l23 + EPS));
            const float dot3 = fabsf(__fdividef(v23x*v34x + v23y*v34y, l23*l34 + EPS));
            const float dot4 = fabsf(__fdividef(v34x*v41x + v34y*v41y, l34*l41 + EPS));
            const float L_edge = (par1 + par2) * 0.5f + (dot1 + dot2 + dot3 + dot4) * 0.25f;

            // ---- L_pos ----
            float dist = 0.0f;
            #pragma unroll
            for (int i = 0; i < 4; i++)
                dist += norm2f(px[i]-gx[i], py[i]-gy[i]);
            dist *= 0.25f;

            const float pax1 = px[1]-px[0], pay1 = py[1]-py[0];
            const float pax2 = px[2]-px[0], pay2 = py[2]-py[0];
            const float pax3 = px[3]-px[0], pay3 = py[3]-py[0];
            const float pred_area = 0.5f * fabsf(pax1*pay2 - pay1*pax2)
                                  + 0.5f * fabsf(pax2*pay3 - pay2*pax3);
            const float gax1 = gx[1]-gx[0], gay1 = gy[1]-gy[0];
            const float gax2 = gx[2]-gx[0], gay2 = gy[2]-gy[0];
            const float gax3 = gx[3]-gx[0], gay3 = gy[3]-gy[0];
            const float gt_area = 0.5f * fabsf(gax1*gay2 - gay1*gax2)
                                + 0.5f * fabsf(gax2*gay3 - gay2*gax3);
            const float area_ratio = __fdividef(fabsf(pred_area - gt_area), gt_area + EPS);

            const float pmx = 0.25f * (px[0]+px[1]+px[2]+px[3]);
            const float pmy = 0.25f * (py[0]+py[1]+py[2]+py[3]);
            const float gmx = 0.25f * (gx[0]+gx[1]+gx[2]+gx[3]);
            const float gmy = 0.25f * (gy[0]+gy[1]+gy[2]+gy[3]);
            float rel_cons = 0.0f;
            #pragma unroll
            for (int i = 0; i < 4; i++)
                rel_cons += norm2f((px[i]-pmx) - (gx[i]-gmx),
                                   (py[i]-pmy) - (gy[i]-gmy));
            rel_cons *= 0.25f;

            const float L_pos = 0.4f * dist + 0.3f * area_ratio + 0.3f * rel_cons;

            L = 0.4f * L_shape + 0.3f * L_edge + 0.3f * L_pos;
            cnt = 1.0f;
        }
    }

    // ---- block reduction (deterministic tree) ----
    #pragma unroll
    for (int off = 16; off > 0; off >>= 1) {
        L   += __shfl_down_sync(0xffffffffu, L,   off);
        cnt += __shfl_down_sync(0xffffffffu, cnt, off);
    }
    const int warp = tid >> 5;
    const int lane = tid & 31;
    if (lane == 0) { sL[warp] = L; sC[warp] = cnt; }
    __syncthreads();
    if (tid == 0) {
        float tL = 0.0f, tC = 0.0f;
        #pragma unroll
        for (int w = 0; w < BLOCK / 32; w++) { tL += sL[w]; tC += sC[w]; }
        g_partials[blockIdx.x] = make_float2(tL, tC);
        __threadfence();
        const unsigned int old = atomicAdd(&g_count, 1u);
        sIsLast = (old == gridDim.x - 1) ? 1 : 0;
    }
    __syncthreads();

    // ---- last block: final reduction (fixed order -> deterministic) ----
    if (sIsLast) {
        float fL = 0.0f, fC = 0.0f;
        const int nblocks = gridDim.x;
        for (int i = tid; i < nblocks; i += BLOCK) {
            float2 v = g_partials[i];
            fL += v.x;
            fC += v.y;
        }
        #pragma unroll
        for (int off = 16; off > 0; off >>= 1) {
            fL += __shfl_down_sync(0xffffffffu, fL, off);
            fC += __shfl_down_sync(0xffffffffu, fC, off);
        }
        if (lane == 0) { sL[warp] = fL; sC[warp] = fC; }
        __syncthreads();
        if (tid == 0) {
            float tL = 0.0f, tC = 0.0f;
            #pragma unroll
            for (int w = 0; w < BLOCK / 32; w++) { tL += sL[w]; tC += sC[w]; }
            out[0] = (tC > 0.5f) ? (tL / tC) : 0.0f;
            g_count = 0;   // reset for next graph replay
        }
    }
}

extern "C" void kernel_launch(void* const* d_in, const int* in_sizes, int n_in,
                              void* d_out, int out_size)
{
    const float* pred = (const float*)d_in[0];
    const float* gt   = (const float*)d_in[1];
    float* out = (float*)d_out;

    const int nrows = in_sizes[0] / 24;   // B*K*3 floats, K=8 -> 24 per row
    int nblocks = (nrows + BLOCK - 1) / BLOCK;   // 524288/256 = 2048
    if (nblocks > MAX_PARTIALS) nblocks = MAX_PARTIALS;

    gsc_fused_kernel<<<nblocks, BLOCK>>>(pred, gt, out, nrows);
}

// round 6
// speedup vs baseline: 1.4396x; 1.2527x over previous
#include <cuda_runtime.h>

#define EPS 1e-6f
#define BLOCK 256
#define MAX_PARTIALS 8192

__device__ float2 g_partials[MAX_PARTIALS];
__device__ unsigned int g_count = 0;

__device__ __forceinline__ float norm2f(float x, float y) {
    return sqrtf(x * x + y * y);
}

__global__ void __launch_bounds__(BLOCK)
gsc_fused_kernel(const float* __restrict__ pred,
                 const float* __restrict__ gt,
                 float* __restrict__ out,
                 int nrows)
{
    __shared__ float sL[BLOCK / 32];
    __shared__ float sC[BLOCK / 32];
    __shared__ int sIsLast;

    const int tid = threadIdx.x;
    const int row = blockIdx.x * BLOCK + tid;

    float L = 0.0f, cnt = 0.0f;

    if (row < nrows) {
        // Row = 24 floats = 6 float4 (96B, 16B aligned). 12 batched LDG.128 -> MLP 12.
        const float4* p4 = reinterpret_cast<const float4*>(pred + (size_t)row * 24);
        const float4* q4 = reinterpret_cast<const float4*>(gt   + (size_t)row * 24);

        float4 rp[6], rg[6];
        #pragma unroll
        for (int i = 0; i < 6; i++) rp[i] = p4[i];
        #pragma unroll
        for (int i = 0; i < 6; i++) rg[i] = q4[i];

        float pv[24], gv[24];
        #pragma unroll
        for (int i = 0; i < 6; i++) {
            pv[4*i+0] = rp[i].x; pv[4*i+1] = rp[i].y; pv[4*i+2] = rp[i].z; pv[4*i+3] = rp[i].w;
            gv[4*i+0] = rg[i].x; gv[4*i+1] = rg[i].y; gv[4*i+2] = rg[i].z; gv[4*i+3] = rg[i].w;
        }

        // First 4 visible keypoints in stable order.
        float px[4], py[4], gx[4], gy[4];
        int nv = 0;
        #pragma unroll
        for (int k = 0; k < 8; k++) {
            const bool vis = (pv[3*k+2] > 0.5f) && (gv[3*k+2] > 0.5f);
            if (vis) {
                const float ax = pv[3*k], ay = pv[3*k+1];
                const float bx = gv[3*k], by = gv[3*k+1];
                if (nv == 0)      { px[0]=ax; py[0]=ay; gx[0]=bx; gy[0]=by; }
                else if (nv == 1) { px[1]=ax; py[1]=ay; gx[1]=bx; gy[1]=by; }
                else if (nv == 2) { px[2]=ax; py[2]=ay; gx[2]=bx; gy[2]=by; }
                else if (nv == 3) { px[3]=ax; py[3]=ay; gx[3]=bx; gy[3]=by; }
                nv++;
            }
        }

        if (nv >= 4) {
            // ---- L_shape ----
            const float pred_cr = __fdividef(norm2f(px[2]-px[0], py[2]-py[0]),
                                             norm2f(px[3]-px[1], py[3]-py[1]) + EPS);
            const float gt_cr   = __fdividef(norm2f(gx[2]-gx[0], gy[2]-gy[0]),
                                             norm2f(gx[3]-gx[1], gy[3]-gy[1]) + EPS);
            const float L_shape = fabsf(pred_cr - gt_cr);

            // ---- L_edge ----
            const float v12x = px[1]-px[0], v12y = py[1]-py[0];
            const float v23x = px[2]-px[1], v23y = py[2]-py[1];
            const float v34x = px[3]-px[2], v34y = py[3]-py[2];
            const float v41x = px[0]-px[3], v41y = py[0]-py[3];
            const float l12 = norm2f(v12x, v12y);
            const float l23 = norm2f(v23x, v23y);
            const float l34 = norm2f(v34x, v34y);
            const float l41 = norm2f(v41x, v41y);

            const float par1 = __fdividef(fabsf(l12 - l34), l12 + l34 + EPS);
            const float par2 = __fdividef(fabsf(l23 - l41), l23 + l41 + EPS);
            const float dot1 = fabsf(__fdividef(v12x*v41x + v12y*v41y, l12*l41 + EPS));
            const float dot2 = fabsf(__fdividef(v12x*v23x + v12y*v23y, l12*l23 + EPS));
            const float dot3 = fabsf(__fdividef(v23x*v34x + v23y*v34y, l23*l34 + EPS));
            const float dot4 = fabsf(__fdividef(v34x*v41x + v34y*v41y, l34*l41 + EPS));
            const float L_edge = (par1 + par2) * 0.5f + (dot1 + dot2 + dot3 + dot4) * 0.25f;

            // ---- L_pos ----
            float dist = 0.0f;
            #pragma unroll
            for (int i = 0; i < 4; i++)
                dist += norm2f(px[i]-gx[i], py[i]-gy[i]);
            dist *= 0.25f;

            const float pax1 = px[1]-px[0], pay1 = py[1]-py[0];
            const float pax2 = px[2]-px[0], pay2 = py[2]-py[0];
            const float pax3 = px[3]-px[0], pay3 = py[3]-py[0];
            const float pred_area = 0.5f * fabsf(pax1*pay2 - pay1*pax2)
                                  + 0.5f * fabsf(pax2*pay3 - pay2*pax3);
            const float gax1 = gx[1]-gx[0], gay1 = gy[1]-gy[0];
            const float gax2 = gx[2]-gx[0], gay2 = gy[2]-gy[0];
            const float gax3 = gx[3]-gx[0], gay3 = gy[3]-gy[0];
            const float gt_area = 0.5f * fabsf(gax1*gay2 - gay1*gax2)
                                + 0.5f * fabsf(gax2*gay3 - gay2*gax3);
            const float area_ratio = __fdividef(fabsf(pred_area - gt_area), gt_area + EPS);

            const float pmx = 0.25f * (px[0]+px[1]+px[2]+px[3]);
            const float pmy = 0.25f * (py[0]+py[1]+py[2]+py[3]);
            const float gmx = 0.25f * (gx[0]+gx[1]+gx[2]+gx[3]);
            const float gmy = 0.25f * (gy[0]+gy[1]+gy[2]+gy[3]);
            float rel_cons = 0.0f;
            #pragma unroll
            for (int i = 0; i < 4; i++)
                rel_cons += norm2f((px[i]-pmx) - (gx[i]-gmx),
                                   (py[i]-pmy) - (gy[i]-gmy));
            rel_cons *= 0.25f;

            const float L_pos = 0.4f * dist + 0.3f * area_ratio + 0.3f * rel_cons;

            L = 0.4f * L_shape + 0.3f * L_edge + 0.3f * L_pos;
            cnt = 1.0f;
        }
    }

    // ---- block reduction (deterministic tree) ----
    #pragma unroll
    for (int off = 16; off > 0; off >>= 1) {
        L   += __shfl_down_sync(0xffffffffu, L,   off);
        cnt += __shfl_down_sync(0xffffffffu, cnt, off);
    }
    const int warp = tid >> 5;
    const int lane = tid & 31;
    if (lane == 0) { sL[warp] = L; sC[warp] = cnt; }
    __syncthreads();
    if (tid == 0) {
        float tL = 0.0f, tC = 0.0f;
        #pragma unroll
        for (int w = 0; w < BLOCK / 32; w++) { tL += sL[w]; tC += sC[w]; }
        g_partials[blockIdx.x] = make_float2(tL, tC);
        __threadfence();
        const unsigned int old = atomicAdd(&g_count, 1u);
        sIsLast = (old == gridDim.x - 1) ? 1 : 0;
    }
    __syncthreads();

    // ---- last block: final reduction (fixed order -> deterministic) ----
    if (sIsLast) {
        float fL = 0.0f, fC = 0.0f;
        const int nblocks = gridDim.x;
        for (int i = tid; i < nblocks; i += BLOCK) {
            float2 v = g_partials[i];
            fL += v.x;
            fC += v.y;
        }
        #pragma unroll
        for (int off = 16; off > 0; off >>= 1) {
            fL += __shfl_down_sync(0xffffffffu, fL, off);
            fC += __shfl_down_sync(0xffffffffu, fC, off);
        }
        if (lane == 0) { sL[warp] = fL; sC[warp] = fC; }
        __syncthreads();
        if (tid == 0) {
            float tL = 0.0f, tC = 0.0f;
            #pragma unroll
            for (int w = 0; w < BLOCK / 32; w++) { tL += sL[w]; tC += sC[w]; }
            out[0] = (tC > 0.5f) ? (tL / tC) : 0.0f;
            g_count = 0;   // reset for next graph replay
        }
    }
}

extern "C" void kernel_launch(void* const* d_in, const int* in_sizes, int n_in,
                              void* d_out, int out_size)
{
    const float* pred = (const float*)d_in[0];
    const float* gt   = (const float*)d_in[1];
    float* out = (float*)d_out;

    const int nrows = in_sizes[0] / 24;   // B*K*3 floats, K=8 -> 24 per row
    int nblocks = (nrows + BLOCK - 1) / BLOCK;   // 524288/256 = 2048
    if (nblocks > MAX_PARTIALS) nblocks = MAX_PARTIALS;

    gsc_fused_kernel<<<nblocks, BLOCK>>>(pred, gt, out, nrows);
}